// round 2
// baseline (speedup 1.0000x reference)
#include <cuda_runtime.h>
#include <math.h>

#define BB 4
#define SS 2048
#define DD 1024
#define HH 16
#define HD 64
#define ROWS (BB*SS)   // 8192

// ---------------- scratch (no allocs allowed) ----------------
__device__ float g_qn[ROWS*DD];
__device__ float g_kn[ROWS*DD];
__device__ float g_vn[ROWS*DD];
__device__ float g_q [ROWS*DD];
__device__ float g_k [ROWS*DD];
__device__ float g_v [ROWS*DD];
__device__ float g_att[ROWS*DD];
__device__ float g_proj[ROWS*DD];
__device__ float g_gate[ROWS];

// ---------------- block reduce ----------------
__device__ __forceinline__ void block_reduce2(float& a, float& b) {
    __shared__ float s1[32], s2[32];
    #pragma unroll
    for (int o = 16; o; o >>= 1) {
        a += __shfl_xor_sync(0xffffffff, a, o);
        b += __shfl_xor_sync(0xffffffff, b, o);
    }
    int w = threadIdx.x >> 5, lane = threadIdx.x & 31;
    int nw = (blockDim.x + 31) >> 5;
    if (lane == 0) { s1[w] = a; s2[w] = b; }
    __syncthreads();
    if (w == 0) {
        a = (lane < nw) ? s1[lane] : 0.f;
        b = (lane < nw) ? s2[lane] : 0.f;
        #pragma unroll
        for (int o = 16; o; o >>= 1) {
            a += __shfl_xor_sync(0xffffffff, a, o);
            b += __shfl_xor_sync(0xffffffff, b, o);
        }
        if (lane == 0) { s1[0] = a; s2[0] = b; }
    }
    __syncthreads();
    a = s1[0]; b = s2[0];
}

// ---------------- layernorm: one block per row, 256 threads ----------------
__global__ __launch_bounds__(256) void ln_kernel(const float* __restrict__ x,
                                                 const float* __restrict__ gg,
                                                 const float* __restrict__ bb,
                                                 float* __restrict__ y) {
    int row = blockIdx.x;
    const float4* xr = (const float4*)(x + (size_t)row * DD);
    int i = threadIdx.x;                // 256 threads, 4 elems each (float4)
    float4 xv = xr[i];
    float sum = xv.x + xv.y + xv.z + xv.w;
    float sq  = xv.x*xv.x + xv.y*xv.y + xv.z*xv.z + xv.w*xv.w;
    block_reduce2(sum, sq);
    float mu = sum * (1.0f / DD);
    float var = sq * (1.0f / DD) - mu * mu;
    float r = rsqrtf(var + 1e-5f);
    float4 gv = ((const float4*)gg)[i];
    float4 bv = ((const float4*)bb)[i];
    float4 o;
    o.x = (xv.x - mu) * r * gv.x + bv.x;
    o.y = (xv.y - mu) * r * gv.y + bv.y;
    o.z = (xv.z - mu) * r * gv.z + bv.z;
    o.w = (xv.w - mu) * r * gv.w + bv.w;
    ((float4*)(y + (size_t)row * DD))[i] = o;
}

// ---------------- GEMM: C[M,D] = A[M,D] @ W[D,D] + bias ----------------
// 128x128 block tile, BK=8, 256 threads, 8x8 microtile (split 2x(4)).
#define BM 128
#define BN 128
#define BK 8
__global__ __launch_bounds__(256) void gemm_bias(const float* __restrict__ A,
                                                 const float* __restrict__ W,
                                                 const float* __restrict__ bias,
                                                 float* __restrict__ C) {
    __shared__ float As[BK][BM];
    __shared__ float Bs[BK][BN];
    int tid = threadIdx.x;
    int tx = tid & 15, ty = tid >> 4;
    int row0 = blockIdx.y * BM;
    int col0 = blockIdx.x * BN;

    float acc[8][8];
    #pragma unroll
    for (int i = 0; i < 8; i++)
        #pragma unroll
        for (int j = 0; j < 8; j++) acc[i][j] = 0.f;

    int a_r = tid >> 1;            // 0..127
    int a_k = (tid & 1) * 4;       // 0 or 4
    int b_k = tid >> 5;            // 0..7
    int b_n = (tid & 31) * 4;      // 0..124

    for (int k0 = 0; k0 < DD; k0 += BK) {
        float4 av = *(const float4*)&A[(size_t)(row0 + a_r) * DD + k0 + a_k];
        As[a_k + 0][a_r] = av.x;
        As[a_k + 1][a_r] = av.y;
        As[a_k + 2][a_r] = av.z;
        As[a_k + 3][a_r] = av.w;
        *(float4*)&Bs[b_k][b_n] = *(const float4*)&W[(size_t)(k0 + b_k) * DD + col0 + b_n];
        __syncthreads();
        #pragma unroll
        for (int kk = 0; kk < BK; kk++) {
            float a[8], b[8];
            *(float4*)&a[0] = *(float4*)&As[kk][ty * 4];
            *(float4*)&a[4] = *(float4*)&As[kk][64 + ty * 4];
            *(float4*)&b[0] = *(float4*)&Bs[kk][tx * 4];
            *(float4*)&b[4] = *(float4*)&Bs[kk][64 + tx * 4];
            #pragma unroll
            for (int i = 0; i < 8; i++)
                #pragma unroll
                for (int j = 0; j < 8; j++)
                    acc[i][j] = fmaf(a[i], b[j], acc[i][j]);
        }
        __syncthreads();
    }

    #pragma unroll
    for (int ih = 0; ih < 2; ih++) {
        #pragma unroll
        for (int i = 0; i < 4; i++) {
            int row = row0 + ih * 64 + ty * 4 + i;
            #pragma unroll
            for (int jh = 0; jh < 2; jh++) {
                int col = col0 + jh * 64 + tx * 4;
                float4 bv = *(const float4*)&bias[col];
                float4 o;
                o.x = acc[ih * 4 + i][jh * 4 + 0] + bv.x;
                o.y = acc[ih * 4 + i][jh * 4 + 1] + bv.y;
                o.z = acc[ih * 4 + i][jh * 4 + 2] + bv.z;
                o.w = acc[ih * 4 + i][jh * 4 + 3] + bv.w;
                *(float4*)&C[(size_t)row * DD + col] = o;
            }
        }
    }
}

// ---------------- gate GEMV: sigmoid(qn @ Wg) ----------------
__global__ __launch_bounds__(128) void gate_kernel(const float* __restrict__ qn,
                                                   const float* __restrict__ Wg,
                                                   float* __restrict__ gate) {
    int row = blockIdx.x;
    const float4* xr = (const float4*)(qn + (size_t)row * DD);
    const float4* wr = (const float4*)Wg;
    float s = 0.f;
    #pragma unroll
    for (int i = threadIdx.x; i < DD / 4; i += 128) {
        float4 xv = xr[i];
        float4 wv = wr[i];
        s += xv.x * wv.x + xv.y * wv.y + xv.z * wv.z + xv.w * wv.w;
    }
    float dummy = 0.f;
    block_reduce2(s, dummy);
    if (threadIdx.x == 0) gate[row] = 1.0f / (1.0f + __expf(-s));
}

// ---------------- flash attention (fp32) ----------------
// 1 thread = 1 query row; q + accumulator in registers; K/V tiles in smem.
__global__ __launch_bounds__(128) void attn_kernel(const float* __restrict__ Q,
                                                   const float* __restrict__ K,
                                                   const float* __restrict__ V,
                                                   float* __restrict__ O) {
    int b = blockIdx.z, h = blockIdx.y;
    int qi = blockIdx.x * 128 + threadIdx.x;
    const float scale = 0.125f;  // 1/sqrt(64)

    __shared__ float k_s[64][68];
    __shared__ float v_s[64][68];

    float q[64];
    const float4* qrow = (const float4*)(Q + ((size_t)(b * SS + qi)) * DD + h * HD);
    #pragma unroll
    for (int d4 = 0; d4 < 16; d4++) {
        float4 t = qrow[d4];
        q[d4 * 4 + 0] = t.x; q[d4 * 4 + 1] = t.y;
        q[d4 * 4 + 2] = t.z; q[d4 * 4 + 3] = t.w;
    }

    float m = -1e30f, l = 0.f;
    float acc[64];
    #pragma unroll
    for (int d = 0; d < 64; d++) acc[d] = 0.f;

    for (int j0 = 0; j0 < SS; j0 += 64) {
        __syncthreads();
        // cooperative load: 64 rows x 16 float4 each for K and V
        for (int t = threadIdx.x; t < 64 * 16; t += 128) {
            int jr = t >> 4, dc = t & 15;
            const float4* krow = (const float4*)(K + ((size_t)(b * SS + j0 + jr)) * DD + h * HD);
            const float4* vrow = (const float4*)(V + ((size_t)(b * SS + j0 + jr)) * DD + h * HD);
            ((float4*)&k_s[jr][0])[dc] = krow[dc];
            ((float4*)&v_s[jr][0])[dc] = vrow[dc];
        }
        __syncthreads();

        #pragma unroll 1
        for (int j = 0; j < 64; j++) {
            const float4* k4 = (const float4*)&k_s[j][0];
            float s = 0.f;
            #pragma unroll
            for (int dd = 0; dd < 16; dd++) {
                float4 kv = k4[dd];
                s = fmaf(q[dd * 4 + 0], kv.x, s);
                s = fmaf(q[dd * 4 + 1], kv.y, s);
                s = fmaf(q[dd * 4 + 2], kv.z, s);
                s = fmaf(q[dd * 4 + 3], kv.w, s);
            }
            s *= scale;
            const float4* v4 = (const float4*)&v_s[j][0];
            if (s <= m) {
                float p = __expf(s - m);
                l += p;
                #pragma unroll
                for (int dd = 0; dd < 16; dd++) {
                    float4 vv = v4[dd];
                    acc[dd * 4 + 0] = fmaf(p, vv.x, acc[dd * 4 + 0]);
                    acc[dd * 4 + 1] = fmaf(p, vv.y, acc[dd * 4 + 1]);
                    acc[dd * 4 + 2] = fmaf(p, vv.z, acc[dd * 4 + 2]);
                    acc[dd * 4 + 3] = fmaf(p, vv.w, acc[dd * 4 + 3]);
                }
            } else {
                float c = __expf(m - s);   // rescale old state (rare)
                m = s;
                l = fmaf(l, c, 1.0f);
                #pragma unroll
                for (int dd = 0; dd < 16; dd++) {
                    float4 vv = v4[dd];
                    acc[dd * 4 + 0] = fmaf(acc[dd * 4 + 0], c, vv.x);
                    acc[dd * 4 + 1] = fmaf(acc[dd * 4 + 1], c, vv.y);
                    acc[dd * 4 + 2] = fmaf(acc[dd * 4 + 2], c, vv.z);
                    acc[dd * 4 + 3] = fmaf(acc[dd * 4 + 3], c, vv.w);
                }
            }
        }
    }

    float inv = 1.0f / l;
    float4* orow = (float4*)(O + ((size_t)(b * SS + qi)) * DD + h * HD);
    #pragma unroll
    for (int dd = 0; dd < 16; dd++) {
        float4 o;
        o.x = acc[dd * 4 + 0] * inv;
        o.y = acc[dd * 4 + 1] * inv;
        o.z = acc[dd * 4 + 2] * inv;
        o.w = acc[dd * 4 + 3] * inv;
        orow[dd] = o;
    }
}

// ---------------- final: out = LN(gate * proj) ----------------
__global__ __launch_bounds__(256) void final_kernel(const float* __restrict__ proj,
                                                    const float* __restrict__ gate,
                                                    const float* __restrict__ gg,
                                                    const float* __restrict__ bb,
                                                    float* __restrict__ out) {
    int row = blockIdx.x;
    float gt = gate[row];
    const float4* xr = (const float4*)(proj + (size_t)row * DD);
    int i = threadIdx.x;
    float4 xv = xr[i];
    xv.x *= gt; xv.y *= gt; xv.z *= gt; xv.w *= gt;
    float sum = xv.x + xv.y + xv.z + xv.w;
    float sq  = xv.x*xv.x + xv.y*xv.y + xv.z*xv.z + xv.w*xv.w;
    block_reduce2(sum, sq);
    float mu = sum * (1.0f / DD);
    float var = sq * (1.0f / DD) - mu * mu;
    float r = rsqrtf(var + 1e-5f);
    float4 gv = ((const float4*)gg)[i];
    float4 bv = ((const float4*)bb)[i];
    float4 o;
    o.x = (xv.x - mu) * r * gv.x + bv.x;
    o.y = (xv.y - mu) * r * gv.y + bv.y;
    o.z = (xv.z - mu) * r * gv.z + bv.z;
    o.w = (xv.w - mu) * r * gv.w + bv.w;
    ((float4*)(out + (size_t)row * DD))[i] = o;
}

// ---------------- launch ----------------
extern "C" void kernel_launch(void* const* d_in, const int* in_sizes, int n_in,
                              void* d_out, int out_size) {
    const float* query = (const float*)d_in[0];
    const float* key   = (const float*)d_in[1];
    const float* value = (const float*)d_in[2];
    const float* Wq = (const float*)d_in[3];
    const float* bq = (const float*)d_in[4];
    const float* Wk = (const float*)d_in[5];
    const float* bk = (const float*)d_in[6];
    const float* Wv = (const float*)d_in[7];
    const float* bv = (const float*)d_in[8];
    const float* Wo = (const float*)d_in[9];
    const float* bo = (const float*)d_in[10];
    const float* Wg = (const float*)d_in[11];
    const float* ln_q_g  = (const float*)d_in[12];
    const float* ln_q_b  = (const float*)d_in[13];
    const float* ln_kv_g = (const float*)d_in[14];
    const float* ln_kv_b = (const float*)d_in[15];
    const float* ln_o_g  = (const float*)d_in[16];
    const float* ln_o_b  = (const float*)d_in[17];
    float* out = (float*)d_out;

    float *qn, *kn, *vn, *q, *k, *v, *att, *proj, *gate;
    cudaGetSymbolAddress((void**)&qn,  g_qn);
    cudaGetSymbolAddress((void**)&kn,  g_kn);
    cudaGetSymbolAddress((void**)&vn,  g_vn);
    cudaGetSymbolAddress((void**)&q,   g_q);
    cudaGetSymbolAddress((void**)&k,   g_k);
    cudaGetSymbolAddress((void**)&v,   g_v);
    cudaGetSymbolAddress((void**)&att, g_att);
    cudaGetSymbolAddress((void**)&proj,g_proj);
    cudaGetSymbolAddress((void**)&gate,g_gate);

    // 1. pre-norms
    ln_kernel<<<ROWS, 256>>>(query, ln_q_g,  ln_q_b,  qn);
    ln_kernel<<<ROWS, 256>>>(key,   ln_kv_g, ln_kv_b, kn);
    ln_kernel<<<ROWS, 256>>>(value, ln_kv_g, ln_kv_b, vn);

    // 2. projections
    dim3 ggrid(DD / BN, ROWS / BM);
    gemm_bias<<<ggrid, 256>>>(qn, Wq, bq, q);
    gemm_bias<<<ggrid, 256>>>(kn, Wk, bk, k);
    gemm_bias<<<ggrid, 256>>>(vn, Wv, bv, v);

    // 3. gate
    gate_kernel<<<ROWS, 128>>>(qn, Wg, gate);

    // 4. attention
    dim3 agrid(SS / 128, HH, BB);
    attn_kernel<<<agrid, 128>>>(q, k, v, att);

    // 5. output projection
    gemm_bias<<<ggrid, 256>>>(att, Wo, bo, proj);

    // 6. gate * proj -> final LN
    final_kernel<<<ROWS, 256>>>(proj, gate, ln_o_g, ln_o_b, out);
}

// round 8
// speedup vs baseline: 1.0928x; 1.0928x over previous
#include <cuda_runtime.h>
#include <cuda_bf16.h>
#include <math.h>
#include <cstdint>

#define BB 4
#define SS 2048
#define DD 1024
#define HH 16
#define HD 64
#define ROWS (BB*SS)   // 8192
#define KTOT 3072      // K' = [hi, lo, hi] x 1024

// ---------------- scratch (no allocs allowed) ----------------
__device__ float g_qn[ROWS*DD];
__device__ float g_kn[ROWS*DD];
__device__ float g_vn[ROWS*DD];
__device__ float g_q [ROWS*DD];
__device__ float g_k [ROWS*DD];
__device__ float g_v [ROWS*DD];
__device__ float g_att[ROWS*DD];
__device__ float g_proj[ROWS*DD];
__device__ float g_gate[ROWS];
__device__ __nv_bfloat16 g_abuf[(size_t)ROWS*KTOT];   // split-A staging (bf16)
__device__ __nv_bfloat16 g_wbuf[(size_t)DD*KTOT];     // split-W^T staging (bf16)

__device__ __forceinline__ uint32_t smem_u32(const void* p) {
    uint32_t a;
    asm("{ .reg .u64 t; cvta.to.shared.u64 t, %1; cvt.u32.u64 %0, t; }" : "=r"(a) : "l"(p));
    return a;
}

#define SWZ128(o) ((o) ^ (((o) >> 3) & 0x70))

// ---------------- block reduce ----------------
__device__ __forceinline__ void block_reduce2(float& a, float& b) {
    __shared__ float s1[32], s2[32];
    #pragma unroll
    for (int o = 16; o; o >>= 1) {
        a += __shfl_xor_sync(0xffffffff, a, o);
        b += __shfl_xor_sync(0xffffffff, b, o);
    }
    int w = threadIdx.x >> 5, lane = threadIdx.x & 31;
    int nw = (blockDim.x + 31) >> 5;
    if (lane == 0) { s1[w] = a; s2[w] = b; }
    __syncthreads();
    if (w == 0) {
        a = (lane < nw) ? s1[lane] : 0.f;
        b = (lane < nw) ? s2[lane] : 0.f;
        #pragma unroll
        for (int o = 16; o; o >>= 1) {
            a += __shfl_xor_sync(0xffffffff, a, o);
            b += __shfl_xor_sync(0xffffffff, b, o);
        }
        if (lane == 0) { s1[0] = a; s2[0] = b; }
    }
    __syncthreads();
    a = s1[0]; b = s2[0];
}

// ---------------- layernorm ----------------
__global__ __launch_bounds__(256) void ln_kernel(const float* __restrict__ x,
                                                 const float* __restrict__ gg,
                                                 const float* __restrict__ bb,
                                                 float* __restrict__ y) {
    int row = blockIdx.x;
    const float4* xr = (const float4*)(x + (size_t)row * DD);
    int i = threadIdx.x;
    float4 xv = xr[i];
    float sum = xv.x + xv.y + xv.z + xv.w;
    float sq  = xv.x*xv.x + xv.y*xv.y + xv.z*xv.z + xv.w*xv.w;
    block_reduce2(sum, sq);
    float mu = sum * (1.0f / DD);
    float var = sq * (1.0f / DD) - mu * mu;
    float r = rsqrtf(var + 1e-5f);
    float4 gv = ((const float4*)gg)[i];
    float4 bv = ((const float4*)bb)[i];
    float4 o;
    o.x = (xv.x - mu) * r * gv.x + bv.x;
    o.y = (xv.y - mu) * r * gv.y + bv.y;
    o.z = (xv.z - mu) * r * gv.z + bv.z;
    o.w = (xv.w - mu) * r * gv.w + bv.w;
    ((float4*)(y + (size_t)row * DD))[i] = o;
}

// ---------------- split A: f32 [8192,1024] -> bf16 [8192,3072] = [hi | lo | hi] ----------------
__global__ __launch_bounds__(256) void split_a(const float* __restrict__ x,
                                               __nv_bfloat16* __restrict__ y) {
    int idx = blockIdx.x * 256 + threadIdx.x;
    float4 v = ((const float4*)x)[idx];
    int row = idx >> 8;
    int c = (idx & 255) * 4;
    __nv_bfloat16 h[4], l[4];
    float vf[4] = {v.x, v.y, v.z, v.w};
    #pragma unroll
    for (int i = 0; i < 4; i++) {
        h[i] = __float2bfloat16(vf[i]);
        l[i] = __float2bfloat16(vf[i] - __bfloat162float(h[i]));
    }
    uint2 hp, lp;
    hp.x = ((uint32_t)__bfloat16_as_ushort(h[1]) << 16) | __bfloat16_as_ushort(h[0]);
    hp.y = ((uint32_t)__bfloat16_as_ushort(h[3]) << 16) | __bfloat16_as_ushort(h[2]);
    lp.x = ((uint32_t)__bfloat16_as_ushort(l[1]) << 16) | __bfloat16_as_ushort(l[0]);
    lp.y = ((uint32_t)__bfloat16_as_ushort(l[3]) << 16) | __bfloat16_as_ushort(l[2]);
    size_t base = (size_t)row * KTOT + c;
    *(uint2*)(y + base)          = hp;   // seg0: hi
    *(uint2*)(y + base + DD)     = lp;   // seg1: lo
    *(uint2*)(y + base + 2*DD)   = hp;   // seg2: hi
}

// ---------------- split+transpose W: f32 [1024,1024] -> bf16 Wt [1024 n, 3072] = [Wh | Wh | Wl] ----------------
__global__ __launch_bounds__(256) void split_wt(const float* __restrict__ W,
                                                __nv_bfloat16* __restrict__ Y) {
    __shared__ float t[32][33];
    int k0 = blockIdx.y * 32, n0 = blockIdx.x * 32;
    int tx = threadIdx.x & 31, ty = threadIdx.x >> 5;
    #pragma unroll
    for (int i = 0; i < 32; i += 8)
        t[ty + i][tx] = W[(size_t)(k0 + ty + i) * DD + n0 + tx];
    __syncthreads();
    #pragma unroll
    for (int i = 0; i < 32; i += 8) {
        int n = ty + i;
        float v = t[tx][n];
        __nv_bfloat16 h = __float2bfloat16(v);
        __nv_bfloat16 l = __float2bfloat16(v - __bfloat162float(h));
        size_t base = (size_t)(n0 + n) * KTOT + k0 + tx;
        Y[base]          = h;
        Y[base + DD]     = h;
        Y[base + 2*DD]   = l;
    }
}

// ---------------- mma.sync bf16 GEMM: C[8192,1024] = Acat @ Wt^T + bias ----------------
// 128x128 CTA tile, 8 warps (2M x 4N), warp tile 64x32, KC=64 chunks, SW128-swizzled smem.
#define KC 64
#define NCHUNK (KTOT / KC)   // 48

__device__ __forceinline__ void ldmx4(uint32_t* r, uint32_t addr) {
    asm volatile("ldmatrix.sync.aligned.m8n8.x4.shared.b16 {%0,%1,%2,%3}, [%4];"
        : "=r"(r[0]), "=r"(r[1]), "=r"(r[2]), "=r"(r[3]) : "r"(addr));
}
__device__ __forceinline__ void mma16816(float* c, const uint32_t* a, const uint32_t* b) {
    asm volatile(
        "mma.sync.aligned.m16n8k16.row.col.f32.bf16.bf16.f32 "
        "{%0,%1,%2,%3}, {%4,%5,%6,%7}, {%8,%9}, {%0,%1,%2,%3};"
        : "+f"(c[0]), "+f"(c[1]), "+f"(c[2]), "+f"(c[3])
        : "r"(a[0]), "r"(a[1]), "r"(a[2]), "r"(a[3]), "r"(b[0]), "r"(b[1]));
}

__global__ __launch_bounds__(256) void gemm_mma(const __nv_bfloat16* __restrict__ A,
                                                const __nv_bfloat16* __restrict__ Bt,
                                                const float* __restrict__ bias,
                                                float* __restrict__ C) {
    __shared__ __align__(1024) char smem[32768];   // A [128][64] bf16 @0, B [128][64] bf16 @16384
    uint32_t sb = smem_u32(smem);
    int tid = threadIdx.x;
    int w = tid >> 5, lane = tid & 31;
    int wm = w & 1, wn = w >> 1;                   // 2 x 4 warp grid
    int row0 = blockIdx.y * 128, col0 = blockIdx.x * 128;

    float acc[4][4][4];
    #pragma unroll
    for (int i = 0; i < 4; i++)
        #pragma unroll
        for (int j = 0; j < 4; j++)
            #pragma unroll
            for (int e = 0; e < 4; e++) acc[i][j][e] = 0.f;

    for (int c = 0; c < NCHUNK; c++) {
        int k0 = c * KC;
        uint4 ra[4], rb[4];
        #pragma unroll
        for (int i = 0; i < 4; i++) {
            int idx = tid + 256 * i;
            int r = idx >> 3, u = idx & 7;
            ra[i] = *(const uint4*)(A  + (size_t)(row0 + r) * KTOT + k0 + u * 8);
            rb[i] = *(const uint4*)(Bt + (size_t)(col0 + r) * KTOT + k0 + u * 8);
        }
        __syncthreads();   // previous chunk's compute done before overwrite
        #pragma unroll
        for (int i = 0; i < 4; i++) {
            int idx = tid + 256 * i;
            int r = idx >> 3, u = idx & 7;
            uint32_t off = r * 128 + u * 16;
            uint32_t sw = SWZ128(off);
            *(uint4*)(smem + sw)         = ra[i];
            *(uint4*)(smem + 16384 + sw) = rb[i];
        }
        __syncthreads();

        #pragma unroll
        for (int k16 = 0; k16 < 4; k16++) {
            // A fragments: 4 m-tiles of 16 rows
            uint32_t af[4][4];
            int ar = wm * 64 + (lane & 15);
            int akc = k16 * 16 + (lane >> 4) * 8;        // k col for this lane
            #pragma unroll
            for (int mt = 0; mt < 4; mt++) {
                uint32_t off = (uint32_t)(ar + mt * 16) * 128 + akc * 2;
                ldmx4(af[mt], sb + SWZ128(off));
            }
            // B fragments: 4 n-tiles of 8 rows; one ldmatrix.x4 covers 2 n-tiles
            uint32_t bf[4][2];
            #pragma unroll
            for (int nt2 = 0; nt2 < 2; nt2++) {
                int bn = wn * 32 + nt2 * 16 + (lane & 7) + ((lane & 16) ? 8 : 0);
                int bkc = k16 * 16 + ((lane >> 3) & 1) * 8;
                uint32_t off = (uint32_t)bn * 128 + bkc * 2;
                uint32_t q[4];
                ldmx4(q, sb + 16384 + SWZ128(off));
                bf[nt2 * 2 + 0][0] = q[0]; bf[nt2 * 2 + 0][1] = q[1];
                bf[nt2 * 2 + 1][0] = q[2]; bf[nt2 * 2 + 1][1] = q[3];
            }
            #pragma unroll
            for (int mt = 0; mt < 4; mt++)
                #pragma unroll
                for (int nt = 0; nt < 4; nt++)
                    mma16816(acc[mt][nt], af[mt], bf[nt]);
        }
    }

    // epilogue: c0,c1 -> (row, col..col+1); c2,c3 -> (row+8, ...)
    #pragma unroll
    for (int mt = 0; mt < 4; mt++) {
        int crow = row0 + wm * 64 + mt * 16 + (lane >> 2);
        #pragma unroll
        for (int nt = 0; nt < 4; nt++) {
            int ccol = col0 + wn * 32 + nt * 8 + (lane & 3) * 2;
            float2 bv = *(const float2*)&bias[ccol];
            float2 o0, o1;
            o0.x = acc[mt][nt][0] + bv.x;
            o0.y = acc[mt][nt][1] + bv.y;
            o1.x = acc[mt][nt][2] + bv.x;
            o1.y = acc[mt][nt][3] + bv.y;
            *(float2*)&C[(size_t)crow * DD + ccol]       = o0;
            *(float2*)&C[(size_t)(crow + 8) * DD + ccol] = o1;
        }
    }
}

// ---------------- gate GEMV: sigmoid(qn @ Wg) ----------------
__global__ __launch_bounds__(128) void gate_kernel(const float* __restrict__ qn,
                                                   const float* __restrict__ Wg,
                                                   float* __restrict__ gate) {
    int row = blockIdx.x;
    const float4* xr = (const float4*)(qn + (size_t)row * DD);
    const float4* wr = (const float4*)Wg;
    float s = 0.f;
    #pragma unroll
    for (int i = threadIdx.x; i < DD / 4; i += 128) {
        float4 xv = xr[i];
        float4 wv = wr[i];
        s += xv.x * wv.x + xv.y * wv.y + xv.z * wv.z + xv.w * wv.w;
    }
    float dummy = 0.f;
    block_reduce2(s, dummy);
    if (threadIdx.x == 0) gate[row] = 1.0f / (1.0f + __expf(-s));
}

// ---------------- flash attention (fp32) ----------------
__global__ __launch_bounds__(128) void attn_kernel(const float* __restrict__ Q,
                                                   const float* __restrict__ K,
                                                   const float* __restrict__ V,
                                                   float* __restrict__ O) {
    int b = blockIdx.z, h = blockIdx.y;
    int qi = blockIdx.x * 128 + threadIdx.x;
    const float scale = 0.125f;  // 1/sqrt(64)

    __shared__ float k_s[64][68];
    __shared__ float v_s[64][68];

    float q[64];
    const float4* qrow = (const float4*)(Q + ((size_t)(b * SS + qi)) * DD + h * HD);
    #pragma unroll
    for (int d4 = 0; d4 < 16; d4++) {
        float4 t = qrow[d4];
        q[d4 * 4 + 0] = t.x; q[d4 * 4 + 1] = t.y;
        q[d4 * 4 + 2] = t.z; q[d4 * 4 + 3] = t.w;
    }

    float m = -1e30f, l = 0.f;
    float acc[64];
    #pragma unroll
    for (int d = 0; d < 64; d++) acc[d] = 0.f;

    for (int j0 = 0; j0 < SS; j0 += 64) {
        __syncthreads();
        for (int t = threadIdx.x; t < 64 * 16; t += 128) {
            int jr = t >> 4, dc = t & 15;
            const float4* krow = (const float4*)(K + ((size_t)(b * SS + j0 + jr)) * DD + h * HD);
            const float4* vrow = (const float4*)(V + ((size_t)(b * SS + j0 + jr)) * DD + h * HD);
            ((float4*)&k_s[jr][0])[dc] = krow[dc];
            ((float4*)&v_s[jr][0])[dc] = vrow[dc];
        }
        __syncthreads();

        #pragma unroll 1
        for (int j = 0; j < 64; j++) {
            const float4* k4 = (const float4*)&k_s[j][0];
            float s = 0.f;
            #pragma unroll
            for (int dd = 0; dd < 16; dd++) {
                float4 kv = k4[dd];
                s = fmaf(q[dd * 4 + 0], kv.x, s);
                s = fmaf(q[dd * 4 + 1], kv.y, s);
                s = fmaf(q[dd * 4 + 2], kv.z, s);
                s = fmaf(q[dd * 4 + 3], kv.w, s);
            }
            s *= scale;
            const float4* v4 = (const float4*)&v_s[j][0];
            if (s <= m) {
                float p = __expf(s - m);
                l += p;
                #pragma unroll
                for (int dd = 0; dd < 16; dd++) {
                    float4 vv = v4[dd];
                    acc[dd * 4 + 0] = fmaf(p, vv.x, acc[dd * 4 + 0]);
                    acc[dd * 4 + 1] = fmaf(p, vv.y, acc[dd * 4 + 1]);
                    acc[dd * 4 + 2] = fmaf(p, vv.z, acc[dd * 4 + 2]);
                    acc[dd * 4 + 3] = fmaf(p, vv.w, acc[dd * 4 + 3]);
                }
            } else {
                float c = __expf(m - s);
                m = s;
                l = fmaf(l, c, 1.0f);
                #pragma unroll
                for (int dd = 0; dd < 16; dd++) {
                    float4 vv = v4[dd];
                    acc[dd * 4 + 0] = fmaf(acc[dd * 4 + 0], c, vv.x);
                    acc[dd * 4 + 1] = fmaf(acc[dd * 4 + 1], c, vv.y);
                    acc[dd * 4 + 2] = fmaf(acc[dd * 4 + 2], c, vv.z);
                    acc[dd * 4 + 3] = fmaf(acc[dd * 4 + 3], c, vv.w);
                }
            }
        }
    }

    float inv = 1.0f / l;
    float4* orow = (float4*)(O + ((size_t)(b * SS + qi)) * DD + h * HD);
    #pragma unroll
    for (int dd = 0; dd < 16; dd++) {
        float4 o;
        o.x = acc[dd * 4 + 0] * inv;
        o.y = acc[dd * 4 + 1] * inv;
        o.z = acc[dd * 4 + 2] * inv;
        o.w = acc[dd * 4 + 3] * inv;
        orow[dd] = o;
    }
}

// ---------------- final: out = LN(gate * proj) ----------------
__global__ __launch_bounds__(256) void final_kernel(const float* __restrict__ proj,
                                                    const float* __restrict__ gate,
                                                    const float* __restrict__ gg,
                                                    const float* __restrict__ bb,
                                                    float* __restrict__ out) {
    int row = blockIdx.x;
    float gt = gate[row];
    const float4* xr = (const float4*)(proj + (size_t)row * DD);
    int i = threadIdx.x;
    float4 xv = xr[i];
    xv.x *= gt; xv.y *= gt; xv.z *= gt; xv.w *= gt;
    float sum = xv.x + xv.y + xv.z + xv.w;
    float sq  = xv.x*xv.x + xv.y*xv.y + xv.z*xv.z + xv.w*xv.w;
    block_reduce2(sum, sq);
    float mu = sum * (1.0f / DD);
    float var = sq * (1.0f / DD) - mu * mu;
    float r = rsqrtf(var + 1e-5f);
    float4 gv = ((const float4*)gg)[i];
    float4 bv = ((const float4*)bb)[i];
    float4 o;
    o.x = (xv.x - mu) * r * gv.x + bv.x;
    o.y = (xv.y - mu) * r * gv.y + bv.y;
    o.z = (xv.z - mu) * r * gv.z + bv.z;
    o.w = (xv.w - mu) * r * gv.w + bv.w;
    ((float4*)(out + (size_t)row * DD))[i] = o;
}

// ---------------- launch ----------------
extern "C" void kernel_launch(void* const* d_in, const int* in_sizes, int n_in,
                              void* d_out, int out_size) {
    const float* query = (const float*)d_in[0];
    const float* key   = (const float*)d_in[1];
    const float* value = (const float*)d_in[2];
    const float* Wq = (const float*)d_in[3];
    const float* bq = (const float*)d_in[4];
    const float* Wk = (const float*)d_in[5];
    const float* bk = (const float*)d_in[6];
    const float* Wv = (const float*)d_in[7];
    const float* bv = (const float*)d_in[8];
    const float* Wo = (const float*)d_in[9];
    const float* bo = (const float*)d_in[10];
    const float* Wg = (const float*)d_in[11];
    const float* ln_q_g  = (const float*)d_in[12];
    const float* ln_q_b  = (const float*)d_in[13];
    const float* ln_kv_g = (const float*)d_in[14];
    const float* ln_kv_b = (const float*)d_in[15];
    const float* ln_o_g  = (const float*)d_in[16];
    const float* ln_o_b  = (const float*)d_in[17];
    float* out = (float*)d_out;

    float *qn, *kn, *vn, *q, *k, *v, *att, *proj, *gate;
    __nv_bfloat16 *abuf, *wbuf;
    cudaGetSymbolAddress((void**)&qn,   g_qn);
    cudaGetSymbolAddress((void**)&kn,   g_kn);
    cudaGetSymbolAddress((void**)&vn,   g_vn);
    cudaGetSymbolAddress((void**)&q,    g_q);
    cudaGetSymbolAddress((void**)&k,    g_k);
    cudaGetSymbolAddress((void**)&v,    g_v);
    cudaGetSymbolAddress((void**)&att,  g_att);
    cudaGetSymbolAddress((void**)&proj, g_proj);
    cudaGetSymbolAddress((void**)&gate, g_gate);
    cudaGetSymbolAddress((void**)&abuf, g_abuf);
    cudaGetSymbolAddress((void**)&wbuf, g_wbuf);

    // 1. pre-norms
    ln_kernel<<<ROWS, 256>>>(query, ln_q_g,  ln_q_b,  qn);
    ln_kernel<<<ROWS, 256>>>(key,   ln_kv_g, ln_kv_b, kn);
    ln_kernel<<<ROWS, 256>>>(value, ln_kv_g, ln_kv_b, vn);

    // 2. gate (depends only on qn)
    gate_kernel<<<ROWS, 128>>>(qn, Wg, gate);

    // 3. projections on tensor cores (hi/lo bf16 split, K'=3072, mma.sync)
    dim3 ggrid(DD / 128, ROWS / 128);
    dim3 wgrid(DD / 32, DD / 32);
    int nblk_a = (ROWS * DD / 4) / 256;

    split_a<<<nblk_a, 256>>>(qn, abuf);
    split_wt<<<wgrid, 256>>>(Wq, wbuf);
    gemm_mma<<<ggrid, 256>>>(abuf, wbuf, bq, q);

    split_a<<<nblk_a, 256>>>(kn, abuf);
    split_wt<<<wgrid, 256>>>(Wk, wbuf);
    gemm_mma<<<ggrid, 256>>>(abuf, wbuf, bk, k);

    split_a<<<nblk_a, 256>>>(vn, abuf);
    split_wt<<<wgrid, 256>>>(Wv, wbuf);
    gemm_mma<<<ggrid, 256>>>(abuf, wbuf, bv, v);

    // 4. attention (fp32)
    dim3 agrid(SS / 128, HH, BB);
    attn_kernel<<<agrid, 128>>>(q, k, v, att);

    // 5. output projection
    split_a<<<nblk_a, 256>>>(att, abuf);
    split_wt<<<wgrid, 256>>>(Wo, wbuf);
    gemm_mma<<<ggrid, 256>>>(abuf, wbuf, bo, proj);

    // 6. gate * proj -> final LN
    final_kernel<<<ROWS, 256>>>(proj, gate, ln_o_g, ln_o_b, out);
}

// round 11
// speedup vs baseline: 1.9834x; 1.8150x over previous
#include <cuda_runtime.h>
#include <cuda_bf16.h>
#include <math.h>
#include <cstdint>

#define BB 4
#define SS 2048
#define DD 1024
#define HH 16
#define HD 64
#define ROWS (BB*SS)   // 8192
#define KTOT 3072      // K' = [hi, lo, hi] x 1024

// ---------------- scratch (no allocs allowed) ----------------
__device__ float g_qn[ROWS*DD];
__device__ float g_kn[ROWS*DD];
__device__ float g_vn[ROWS*DD];
__device__ float g_q [ROWS*DD];
__device__ float g_k [ROWS*DD];
__device__ float g_v [ROWS*DD];
__device__ float g_att[ROWS*DD];
__device__ float g_proj[ROWS*DD];
__device__ float g_gate[ROWS];
__device__ __nv_bfloat16 g_abuf[(size_t)ROWS*KTOT];      // split-A staging (bf16)
__device__ __nv_bfloat16 g_wbuf[(size_t)DD*KTOT];        // split-W^T staging (bf16)
__device__ __nv_bfloat16 g_qsp[(size_t)BB*HH*SS*192];    // per-head Q split [qh|ql|qh]
__device__ __nv_bfloat16 g_ksp[(size_t)BB*HH*SS*192];    // per-head K split [kh|kh|kl]
__device__ __nv_bfloat16 g_vth[(size_t)BB*DD*SS];        // V^T hi: [b*1024+dcol][s]
__device__ __nv_bfloat16 g_vtl[(size_t)BB*DD*SS];        // V^T lo

__device__ __forceinline__ uint32_t smem_u32(const void* p) {
    uint32_t a;
    asm("{ .reg .u64 t; cvta.to.shared.u64 t, %1; cvt.u32.u64 %0, t; }" : "=r"(a) : "l"(p));
    return a;
}

#define SWZ128(o) ((o) ^ (((o) >> 3) & 0x70))

__device__ __forceinline__ void ldmx4(uint32_t* r, uint32_t addr) {
    asm volatile("ldmatrix.sync.aligned.m8n8.x4.shared.b16 {%0,%1,%2,%3}, [%4];"
        : "=r"(r[0]), "=r"(r[1]), "=r"(r[2]), "=r"(r[3]) : "r"(addr));
}
__device__ __forceinline__ void mma16816(float* c, const uint32_t* a, const uint32_t* b) {
    asm volatile(
        "mma.sync.aligned.m16n8k16.row.col.f32.bf16.bf16.f32 "
        "{%0,%1,%2,%3}, {%4,%5,%6,%7}, {%8,%9}, {%0,%1,%2,%3};"
        : "+f"(c[0]), "+f"(c[1]), "+f"(c[2]), "+f"(c[3])
        : "r"(a[0]), "r"(a[1]), "r"(a[2]), "r"(a[3]), "r"(b[0]), "r"(b[1]));
}
__device__ __forceinline__ uint32_t packbf(float lo, float hi) {
    uint32_t r;
    asm("cvt.rn.bf16x2.f32 %0, %1, %2;" : "=r"(r) : "f"(hi), "f"(lo));  // first src -> high
    return r;
}

// ---------------- block reduce ----------------
__device__ __forceinline__ void block_reduce2(float& a, float& b) {
    __shared__ float s1[32], s2[32];
    #pragma unroll
    for (int o = 16; o; o >>= 1) {
        a += __shfl_xor_sync(0xffffffff, a, o);
        b += __shfl_xor_sync(0xffffffff, b, o);
    }
    int w = threadIdx.x >> 5, lane = threadIdx.x & 31;
    int nw = (blockDim.x + 31) >> 5;
    if (lane == 0) { s1[w] = a; s2[w] = b; }
    __syncthreads();
    if (w == 0) {
        a = (lane < nw) ? s1[lane] : 0.f;
        b = (lane < nw) ? s2[lane] : 0.f;
        #pragma unroll
        for (int o = 16; o; o >>= 1) {
            a += __shfl_xor_sync(0xffffffff, a, o);
            b += __shfl_xor_sync(0xffffffff, b, o);
        }
        if (lane == 0) { s1[0] = a; s2[0] = b; }
    }
    __syncthreads();
    a = s1[0]; b = s2[0];
}

// ---------------- layernorm ----------------
__global__ __launch_bounds__(256) void ln_kernel(const float* __restrict__ x,
                                                 const float* __restrict__ gg,
                                                 const float* __restrict__ bb,
                                                 float* __restrict__ y) {
    int row = blockIdx.x;
    const float4* xr = (const float4*)(x + (size_t)row * DD);
    int i = threadIdx.x;
    float4 xv = xr[i];
    float sum = xv.x + xv.y + xv.z + xv.w;
    float sq  = xv.x*xv.x + xv.y*xv.y + xv.z*xv.z + xv.w*xv.w;
    block_reduce2(sum, sq);
    float mu = sum * (1.0f / DD);
    float var = sq * (1.0f / DD) - mu * mu;
    float r = rsqrtf(var + 1e-5f);
    float4 gv = ((const float4*)gg)[i];
    float4 bv = ((const float4*)bb)[i];
    float4 o;
    o.x = (xv.x - mu) * r * gv.x + bv.x;
    o.y = (xv.y - mu) * r * gv.y + bv.y;
    o.z = (xv.z - mu) * r * gv.z + bv.z;
    o.w = (xv.w - mu) * r * gv.w + bv.w;
    ((float4*)(y + (size_t)row * DD))[i] = o;
}

// ---------------- split A: f32 [8192,1024] -> bf16 [8192,3072] = [hi | lo | hi] ----------------
__global__ __launch_bounds__(256) void split_a(const float* __restrict__ x,
                                               __nv_bfloat16* __restrict__ y) {
    int idx = blockIdx.x * 256 + threadIdx.x;
    float4 v = ((const float4*)x)[idx];
    int row = idx >> 8;
    int c = (idx & 255) * 4;
    __nv_bfloat16 h[4], l[4];
    float vf[4] = {v.x, v.y, v.z, v.w};
    #pragma unroll
    for (int i = 0; i < 4; i++) {
        h[i] = __float2bfloat16(vf[i]);
        l[i] = __float2bfloat16(vf[i] - __bfloat162float(h[i]));
    }
    uint2 hp, lp;
    hp.x = ((uint32_t)__bfloat16_as_ushort(h[1]) << 16) | __bfloat16_as_ushort(h[0]);
    hp.y = ((uint32_t)__bfloat16_as_ushort(h[3]) << 16) | __bfloat16_as_ushort(h[2]);
    lp.x = ((uint32_t)__bfloat16_as_ushort(l[1]) << 16) | __bfloat16_as_ushort(l[0]);
    lp.y = ((uint32_t)__bfloat16_as_ushort(l[3]) << 16) | __bfloat16_as_ushort(l[2]);
    size_t base = (size_t)row * KTOT + c;
    *(uint2*)(y + base)          = hp;
    *(uint2*)(y + base + DD)     = lp;
    *(uint2*)(y + base + 2*DD)   = hp;
}

// ---------------- split+transpose W -> bf16 Wt [n][3072] = [Wh | Wh | Wl] ----------------
__global__ __launch_bounds__(256) void split_wt(const float* __restrict__ W,
                                                __nv_bfloat16* __restrict__ Y) {
    __shared__ float t[32][33];
    int k0 = blockIdx.y * 32, n0 = blockIdx.x * 32;
    int tx = threadIdx.x & 31, ty = threadIdx.x >> 5;
    #pragma unroll
    for (int i = 0; i < 32; i += 8)
        t[ty + i][tx] = W[(size_t)(k0 + ty + i) * DD + n0 + tx];
    __syncthreads();
    #pragma unroll
    for (int i = 0; i < 32; i += 8) {
        int n = ty + i;
        float v = t[tx][n];
        __nv_bfloat16 h = __float2bfloat16(v);
        __nv_bfloat16 l = __float2bfloat16(v - __bfloat162float(h));
        size_t base = (size_t)(n0 + n) * KTOT + k0 + tx;
        Y[base]          = h;
        Y[base + DD]     = h;
        Y[base + 2*DD]   = l;
    }
}

// ---------------- per-head split for attention: Q mode [qh|ql|qh], K mode [kh|kh|kl] ----------------
__global__ __launch_bounds__(256) void hsplit(const float* __restrict__ X,
                                              __nv_bfloat16* __restrict__ Y, int kmode) {
    int row = blockIdx.x;
    int col = threadIdx.x * 4;
    float4 v = *(const float4*)(X + (size_t)row * DD + col);
    int b = row >> 11, s = row & 2047, h = col >> 6, c = col & 63;
    __nv_bfloat16 hh[4], ll[4];
    float vf[4] = {v.x, v.y, v.z, v.w};
    #pragma unroll
    for (int i = 0; i < 4; i++) {
        hh[i] = __float2bfloat16(vf[i]);
        ll[i] = __float2bfloat16(vf[i] - __bfloat162float(hh[i]));
    }
    uint2 hp, lp;
    hp.x = ((uint32_t)__bfloat16_as_ushort(hh[1]) << 16) | __bfloat16_as_ushort(hh[0]);
    hp.y = ((uint32_t)__bfloat16_as_ushort(hh[3]) << 16) | __bfloat16_as_ushort(hh[2]);
    lp.x = ((uint32_t)__bfloat16_as_ushort(ll[1]) << 16) | __bfloat16_as_ushort(ll[0]);
    lp.y = ((uint32_t)__bfloat16_as_ushort(ll[3]) << 16) | __bfloat16_as_ushort(ll[2]);
    __nv_bfloat16* out = Y + ((size_t)(b * HH + h) * SS + s) * 192 + c;
    if (kmode) {
        *(uint2*)out         = hp;
        *(uint2*)(out + 64)  = hp;
        *(uint2*)(out + 128) = lp;
    } else {
        *(uint2*)out         = hp;
        *(uint2*)(out + 64)  = lp;
        *(uint2*)(out + 128) = hp;
    }
}

// ---------------- V transpose + split: [b*S+s][dcol] -> Vh/Vl [b*1024+dcol][s] ----------------
__global__ __launch_bounds__(256) void vt_split(const float* __restrict__ V,
                                                __nv_bfloat16* __restrict__ Vh,
                                                __nv_bfloat16* __restrict__ Vl) {
    __shared__ float t[32][33];
    int s0 = blockIdx.x * 32, d0 = blockIdx.y * 32, b = blockIdx.z;
    int tx = threadIdx.x & 31, ty = threadIdx.x >> 5;
    #pragma unroll
    for (int i = 0; i < 32; i += 8)
        t[ty + i][tx] = V[((size_t)b * SS + s0 + ty + i) * DD + d0 + tx];
    __syncthreads();
    #pragma unroll
    for (int i = 0; i < 32; i += 8) {
        int d = ty + i;
        float v = t[tx][d];
        __nv_bfloat16 h = __float2bfloat16(v);
        __nv_bfloat16 l = __float2bfloat16(v - __bfloat162float(h));
        size_t o = ((size_t)b * DD + d0 + d) * SS + s0 + tx;
        Vh[o] = h; Vl[o] = l;
    }
}

// ---------------- mma.sync bf16 GEMM (validated R8) ----------------
#define KC 64
#define NCHUNK (KTOT / KC)   // 48

__global__ __launch_bounds__(256) void gemm_mma(const __nv_bfloat16* __restrict__ A,
                                                const __nv_bfloat16* __restrict__ Bt,
                                                const float* __restrict__ bias,
                                                float* __restrict__ C) {
    __shared__ __align__(1024) char smem[32768];
    uint32_t sb = smem_u32(smem);
    int tid = threadIdx.x;
    int w = tid >> 5, lane = tid & 31;
    int wm = w & 1, wn = w >> 1;
    int row0 = blockIdx.y * 128, col0 = blockIdx.x * 128;

    float acc[4][4][4];
    #pragma unroll
    for (int i = 0; i < 4; i++)
        #pragma unroll
        for (int j = 0; j < 4; j++)
            #pragma unroll
            for (int e = 0; e < 4; e++) acc[i][j][e] = 0.f;

    for (int c = 0; c < NCHUNK; c++) {
        int k0 = c * KC;
        uint4 ra[4], rb[4];
        #pragma unroll
        for (int i = 0; i < 4; i++) {
            int idx = tid + 256 * i;
            int r = idx >> 3, u = idx & 7;
            ra[i] = *(const uint4*)(A  + (size_t)(row0 + r) * KTOT + k0 + u * 8);
            rb[i] = *(const uint4*)(Bt + (size_t)(col0 + r) * KTOT + k0 + u * 8);
        }
        __syncthreads();
        #pragma unroll
        for (int i = 0; i < 4; i++) {
            int idx = tid + 256 * i;
            int r = idx >> 3, u = idx & 7;
            uint32_t sw = SWZ128((uint32_t)(r * 128 + u * 16));
            *(uint4*)(smem + sw)         = ra[i];
            *(uint4*)(smem + 16384 + sw) = rb[i];
        }
        __syncthreads();

        #pragma unroll
        for (int k16 = 0; k16 < 4; k16++) {
            uint32_t af[4][4];
            int ar = wm * 64 + (lane & 15);
            int akc = k16 * 16 + (lane >> 4) * 8;
            #pragma unroll
            for (int mt = 0; mt < 4; mt++)
                ldmx4(af[mt], sb + SWZ128((uint32_t)((ar + mt * 16) * 128 + akc * 2)));
            uint32_t bf[4][2];
            #pragma unroll
            for (int nt2 = 0; nt2 < 2; nt2++) {
                int bn = wn * 32 + nt2 * 16 + (lane & 7) + ((lane & 16) ? 8 : 0);
                int bkc = k16 * 16 + ((lane >> 3) & 1) * 8;
                uint32_t q[4];
                ldmx4(q, sb + 16384 + SWZ128((uint32_t)(bn * 128 + bkc * 2)));
                bf[nt2 * 2 + 0][0] = q[0]; bf[nt2 * 2 + 0][1] = q[1];
                bf[nt2 * 2 + 1][0] = q[2]; bf[nt2 * 2 + 1][1] = q[3];
            }
            #pragma unroll
            for (int mt = 0; mt < 4; mt++)
                #pragma unroll
                for (int nt = 0; nt < 4; nt++)
                    mma16816(acc[mt][nt], af[mt], bf[nt]);
        }
    }

    #pragma unroll
    for (int mt = 0; mt < 4; mt++) {
        int crow = row0 + wm * 64 + mt * 16 + (lane >> 2);
        #pragma unroll
        for (int nt = 0; nt < 4; nt++) {
            int ccol = col0 + wn * 32 + nt * 8 + (lane & 3) * 2;
            float2 bv = *(const float2*)&bias[ccol];
            float2 o0, o1;
            o0.x = acc[mt][nt][0] + bv.x;
            o0.y = acc[mt][nt][1] + bv.y;
            o1.x = acc[mt][nt][2] + bv.x;
            o1.y = acc[mt][nt][3] + bv.y;
            *(float2*)&C[(size_t)crow * DD + ccol]       = o0;
            *(float2*)&C[(size_t)(crow + 8) * DD + ccol] = o1;
        }
    }
}

// ---------------- mma flash attention ----------------
// CTA: 128 q-rows x one (b,h); 8 warps x 16 rows; 64-key chunks.
// smem: Q [128][384B] @0, K [64][384B] @49152, VH [64][128B] @73728, VL @81920.
#define SMEM_ATT 90112

__global__ __launch_bounds__(256) void attn_mma(const __nv_bfloat16* __restrict__ Qs,
                                                const __nv_bfloat16* __restrict__ Ks,
                                                const __nv_bfloat16* __restrict__ Vh,
                                                const __nv_bfloat16* __restrict__ Vl,
                                                float* __restrict__ O) {
    extern __shared__ __align__(1024) char sm[];
    uint32_t sb = smem_u32(sm);
    const uint32_t SQ = 0, SK = 49152, SVH = 73728, SVL = 81920;
    int tid = threadIdx.x, w = tid >> 5, lane = tid & 31;
    int qt = blockIdx.x, bh = blockIdx.y;
    int b = bh >> 4, h = bh & 15;
    size_t qrow0 = (size_t)bh * SS + qt * 128;
    size_t krow0 = (size_t)bh * SS;
    size_t vrow0 = (size_t)b * DD + h * HD;

    // stage Q once: 128 rows x 24 16B-units
    #pragma unroll
    for (int i = 0; i < 12; i++) {
        int idx = tid + 256 * i;
        int row = idx / 24, u = idx % 24;
        uint4 v = *(const uint4*)(Qs + (qrow0 + row) * 192 + u * 8);
        *(uint4*)(sm + SQ + SWZ128((uint32_t)(row * 384 + u * 16))) = v;
    }

    float oacc[8][4];
    #pragma unroll
    for (int nt = 0; nt < 8; nt++)
        #pragma unroll
        for (int e = 0; e < 4; e++) oacc[nt][e] = 0.f;
    float m0 = -1e30f, m1 = -1e30f, l0 = 0.f, l1 = 0.f;

    for (int ch = 0; ch < SS / 64; ch++) {
        __syncthreads();
        // stage K chunk: 64 rows x 24 units
        #pragma unroll
        for (int i = 0; i < 6; i++) {
            int idx = tid + 256 * i;
            int row = idx / 24, u = idx % 24;
            uint4 v = *(const uint4*)(Ks + (krow0 + ch * 64 + row) * 192 + u * 8);
            *(uint4*)(sm + SK + SWZ128((uint32_t)(row * 384 + u * 16))) = v;
        }
        // stage V chunk: 64 d-rows x 8 units (hi and lo)
        #pragma unroll
        for (int i = 0; i < 2; i++) {
            int idx = tid + 256 * i;
            int d = idx >> 3, u = idx & 7;
            uint32_t sw = SWZ128((uint32_t)(d * 128 + u * 16));
            *(uint4*)(sm + SVH + sw) = *(const uint4*)(Vh + (vrow0 + d) * SS + ch * 64 + u * 8);
            *(uint4*)(sm + SVL + sw) = *(const uint4*)(Vl + (vrow0 + d) * SS + ch * 64 + u * 8);
        }
        __syncthreads();

        // S = Q K^T (3-term split over 192 k-dim)
        float sf[8][4];
        #pragma unroll
        for (int nt = 0; nt < 8; nt++)
            #pragma unroll
            for (int e = 0; e < 4; e++) sf[nt][e] = 0.f;

        #pragma unroll
        for (int kb = 0; kb < 12; kb++) {
            uint32_t a[4];
            int ar = w * 16 + (lane & 15);
            int akc = kb * 16 + (lane >> 4) * 8;
            ldmx4(a, sb + SQ + SWZ128((uint32_t)(ar * 384 + akc * 2)));
            uint32_t bf[8][2];
            #pragma unroll
            for (int nt2 = 0; nt2 < 4; nt2++) {
                int bn = nt2 * 16 + (lane & 7) + ((lane & 16) ? 8 : 0);
                int bkc = kb * 16 + ((lane >> 3) & 1) * 8;
                uint32_t q[4];
                ldmx4(q, sb + SK + SWZ128((uint32_t)(bn * 384 + bkc * 2)));
                bf[nt2 * 2 + 0][0] = q[0]; bf[nt2 * 2 + 0][1] = q[1];
                bf[nt2 * 2 + 1][0] = q[2]; bf[nt2 * 2 + 1][1] = q[3];
            }
            #pragma unroll
            for (int nt = 0; nt < 8; nt++) mma16816(sf[nt], a, bf[nt]);
        }

        // online softmax (rows r = lane>>2 and r+8)
        float mr0 = -1e30f, mr1 = -1e30f;
        #pragma unroll
        for (int nt = 0; nt < 8; nt++) {
            #pragma unroll
            for (int e = 0; e < 4; e++) sf[nt][e] *= 0.125f;
            mr0 = fmaxf(mr0, fmaxf(sf[nt][0], sf[nt][1]));
            mr1 = fmaxf(mr1, fmaxf(sf[nt][2], sf[nt][3]));
        }
        mr0 = fmaxf(mr0, __shfl_xor_sync(0xffffffff, mr0, 1));
        mr0 = fmaxf(mr0, __shfl_xor_sync(0xffffffff, mr0, 2));
        mr1 = fmaxf(mr1, __shfl_xor_sync(0xffffffff, mr1, 1));
        mr1 = fmaxf(mr1, __shfl_xor_sync(0xffffffff, mr1, 2));
        float nm0 = fmaxf(m0, mr0), nm1 = fmaxf(m1, mr1);
        float f0 = __expf(m0 - nm0), f1 = __expf(m1 - nm1);
        m0 = nm0; m1 = nm1;
        float s0 = 0.f, s1 = 0.f;
        #pragma unroll
        for (int nt = 0; nt < 8; nt++) {
            sf[nt][0] = __expf(sf[nt][0] - m0);
            sf[nt][1] = __expf(sf[nt][1] - m0);
            sf[nt][2] = __expf(sf[nt][2] - m1);
            sf[nt][3] = __expf(sf[nt][3] - m1);
            s0 += sf[nt][0] + sf[nt][1];
            s1 += sf[nt][2] + sf[nt][3];
        }
        s0 += __shfl_xor_sync(0xffffffff, s0, 1);
        s0 += __shfl_xor_sync(0xffffffff, s0, 2);
        s1 += __shfl_xor_sync(0xffffffff, s1, 1);
        s1 += __shfl_xor_sync(0xffffffff, s1, 2);
        l0 = l0 * f0 + s0;
        l1 = l1 * f1 + s1;
        #pragma unroll
        for (int nt = 0; nt < 8; nt++) {
            oacc[nt][0] *= f0; oacc[nt][1] *= f0;
            oacc[nt][2] *= f1; oacc[nt][3] *= f1;
        }

        // P fragments (C-frag -> A-frag direct) + residuals
        uint32_t ah[4][4], al[4][4];
        #pragma unroll
        for (int kb = 0; kb < 4; kb++) {
            #pragma unroll
            for (int half = 0; half < 2; half++) {          // tiles 2kb, 2kb+1
                const float* p = sf[2 * kb + half];
                float h0 = __bfloat162float(__float2bfloat16(p[0]));
                float h1 = __bfloat162float(__float2bfloat16(p[1]));
                float h2 = __bfloat162float(__float2bfloat16(p[2]));
                float h3 = __bfloat162float(__float2bfloat16(p[3]));
                ah[kb][half * 2 + 0] = packbf(p[0], p[1]);
                ah[kb][half * 2 + 1] = packbf(p[2], p[3]);
                al[kb][half * 2 + 0] = packbf(p[0] - h0, p[1] - h1);
                al[kb][half * 2 + 1] = packbf(p[2] - h2, p[3] - h3);
            }
        }

        // O += [ph|pl|ph] x [vh|vh|vl]
        #pragma unroll
        for (int kb = 0; kb < 12; kb++) {
            const uint32_t* a = (kb < 4) ? ah[kb] : (kb < 8) ? al[kb - 4] : ah[kb - 8];
            uint32_t vbase_sm = (kb < 8) ? SVH : SVL;
            int vkb = kb & 3;
            uint32_t bf[8][2];
            #pragma unroll
            for (int nt2 = 0; nt2 < 4; nt2++) {
                int bn = nt2 * 16 + (lane & 7) + ((lane & 16) ? 8 : 0);   // d row
                int bkc = vkb * 16 + ((lane >> 3) & 1) * 8;               // key col
                uint32_t q[4];
                ldmx4(q, sb + vbase_sm + SWZ128((uint32_t)(bn * 128 + bkc * 2)));
                bf[nt2 * 2 + 0][0] = q[0]; bf[nt2 * 2 + 0][1] = q[1];
                bf[nt2 * 2 + 1][0] = q[2]; bf[nt2 * 2 + 1][1] = q[3];
            }
            #pragma unroll
            for (int nt = 0; nt < 8; nt++) mma16816(oacc[nt], a, bf[nt]);
        }
    }

    // epilogue
    float i0 = 1.f / l0, i1 = 1.f / l1;
    size_t grow = (size_t)b * SS + qt * 128 + w * 16 + (lane >> 2);
    #pragma unroll
    for (int nt = 0; nt < 8; nt++) {
        int col = h * HD + nt * 8 + (lane & 3) * 2;
        float2 o0, o1;
        o0.x = oacc[nt][0] * i0; o0.y = oacc[nt][1] * i0;
        o1.x = oacc[nt][2] * i1; o1.y = oacc[nt][3] * i1;
        *(float2*)&O[grow * DD + col]       = o0;
        *(float2*)&O[(grow + 8) * DD + col] = o1;
    }
}

// ---------------- gate GEMV ----------------
__global__ __launch_bounds__(128) void gate_kernel(const float* __restrict__ qn,
                                                   const float* __restrict__ Wg,
                                                   float* __restrict__ gate) {
    int row = blockIdx.x;
    const float4* xr = (const float4*)(qn + (size_t)row * DD);
    const float4* wr = (const float4*)Wg;
    float s = 0.f;
    #pragma unroll
    for (int i = threadIdx.x; i < DD / 4; i += 128) {
        float4 xv = xr[i];
        float4 wv = wr[i];
        s += xv.x * wv.x + xv.y * wv.y + xv.z * wv.z + xv.w * wv.w;
    }
    float dummy = 0.f;
    block_reduce2(s, dummy);
    if (threadIdx.x == 0) gate[row] = 1.0f / (1.0f + __expf(-s));
}

// ---------------- final: out = LN(gate * proj) ----------------
__global__ __launch_bounds__(256) void final_kernel(const float* __restrict__ proj,
                                                    const float* __restrict__ gate,
                                                    const float* __restrict__ gg,
                                                    const float* __restrict__ bb,
                                                    float* __restrict__ out) {
    int row = blockIdx.x;
    float gt = gate[row];
    const float4* xr = (const float4*)(proj + (size_t)row * DD);
    int i = threadIdx.x;
    float4 xv = xr[i];
    xv.x *= gt; xv.y *= gt; xv.z *= gt; xv.w *= gt;
    float sum = xv.x + xv.y + xv.z + xv.w;
    float sq  = xv.x*xv.x + xv.y*xv.y + xv.z*xv.z + xv.w*xv.w;
    block_reduce2(sum, sq);
    float mu = sum * (1.0f / DD);
    float var = sq * (1.0f / DD) - mu * mu;
    float r = rsqrtf(var + 1e-5f);
    float4 gv = ((const float4*)gg)[i];
    float4 bv = ((const float4*)bb)[i];
    float4 o;
    o.x = (xv.x - mu) * r * gv.x + bv.x;
    o.y = (xv.y - mu) * r * gv.y + bv.y;
    o.z = (xv.z - mu) * r * gv.z + bv.z;
    o.w = (xv.w - mu) * r * gv.w + bv.w;
    ((float4*)(out + (size_t)row * DD))[i] = o;
}

// ---------------- launch ----------------
extern "C" void kernel_launch(void* const* d_in, const int* in_sizes, int n_in,
                              void* d_out, int out_size) {
    const float* query = (const float*)d_in[0];
    const float* key   = (const float*)d_in[1];
    const float* value = (const float*)d_in[2];
    const float* Wq = (const float*)d_in[3];
    const float* bq = (const float*)d_in[4];
    const float* Wk = (const float*)d_in[5];
    const float* bk = (const float*)d_in[6];
    const float* Wv = (const float*)d_in[7];
    const float* bv = (const float*)d_in[8];
    const float* Wo = (const float*)d_in[9];
    const float* bo = (const float*)d_in[10];
    const float* Wg = (const float*)d_in[11];
    const float* ln_q_g  = (const float*)d_in[12];
    const float* ln_q_b  = (const float*)d_in[13];
    const float* ln_kv_g = (const float*)d_in[14];
    const float* ln_kv_b = (const float*)d_in[15];
    const float* ln_o_g  = (const float*)d_in[16];
    const float* ln_o_b  = (const float*)d_in[17];
    float* out = (float*)d_out;

    float *qn, *kn, *vn, *q, *k, *v, *att, *proj, *gate;
    __nv_bfloat16 *abuf, *wbuf, *qsp, *ksp, *vth, *vtl;
    cudaGetSymbolAddress((void**)&qn,   g_qn);
    cudaGetSymbolAddress((void**)&kn,   g_kn);
    cudaGetSymbolAddress((void**)&vn,   g_vn);
    cudaGetSymbolAddress((void**)&q,    g_q);
    cudaGetSymbolAddress((void**)&k,    g_k);
    cudaGetSymbolAddress((void**)&v,    g_v);
    cudaGetSymbolAddress((void**)&att,  g_att);
    cudaGetSymbolAddress((void**)&proj, g_proj);
    cudaGetSymbolAddress((void**)&gate, g_gate);
    cudaGetSymbolAddress((void**)&abuf, g_abuf);
    cudaGetSymbolAddress((void**)&wbuf, g_wbuf);
    cudaGetSymbolAddress((void**)&qsp,  g_qsp);
    cudaGetSymbolAddress((void**)&ksp,  g_ksp);
    cudaGetSymbolAddress((void**)&vth,  g_vth);
    cudaGetSymbolAddress((void**)&vtl,  g_vtl);

    cudaFuncSetAttribute(attn_mma, cudaFuncAttributeMaxDynamicSharedMemorySize, SMEM_ATT);

    // 1. pre-norms
    ln_kernel<<<ROWS, 256>>>(query, ln_q_g,  ln_q_b,  qn);
    ln_kernel<<<ROWS, 256>>>(key,   ln_kv_g, ln_kv_b, kn);
    ln_kernel<<<ROWS, 256>>>(value, ln_kv_g, ln_kv_b, vn);

    // 2. gate
    gate_kernel<<<ROWS, 128>>>(qn, Wg, gate);

    // 3. projections (hi/lo bf16 split, mma.sync)
    dim3 ggrid(DD / 128, ROWS / 128);
    dim3 wgrid(DD / 32, DD / 32);
    int nblk_a = (ROWS * DD / 4) / 256;

    split_a<<<nblk_a, 256>>>(qn, abuf);
    split_wt<<<wgrid, 256>>>(Wq, wbuf);
    gemm_mma<<<ggrid, 256>>>(abuf, wbuf, bq, q);

    split_a<<<nblk_a, 256>>>(kn, abuf);
    split_wt<<<wgrid, 256>>>(Wk, wbuf);
    gemm_mma<<<ggrid, 256>>>(abuf, wbuf, bk, k);

    split_a<<<nblk_a, 256>>>(vn, abuf);
    split_wt<<<wgrid, 256>>>(Wv, wbuf);
    gemm_mma<<<ggrid, 256>>>(abuf, wbuf, bv, v);

    // 4. attention operand prep + mma flash attention
    hsplit<<<ROWS, 256>>>(q, qsp, 0);
    hsplit<<<ROWS, 256>>>(k, ksp, 1);
    dim3 vgrid(SS / 32, DD / 32, BB);
    vt_split<<<vgrid, 256>>>(v, vth, vtl);
    dim3 agrid(SS / 128, BB * HH);
    attn_mma<<<agrid, 256, SMEM_ATT>>>(qsp, ksp, vth, vtl, att);

    // 5. output projection
    split_a<<<nblk_a, 256>>>(att, abuf);
    split_wt<<<wgrid, 256>>>(Wo, wbuf);
    gemm_mma<<<ggrid, 256>>>(abuf, wbuf, bo, proj);

    // 6. gate * proj -> final LN
    final_kernel<<<ROWS, 256>>>(proj, gate, ln_o_g, ln_o_b, out);
}

// round 14
// speedup vs baseline: 3.1382x; 1.5822x over previous
#include <cuda_runtime.h>
#include <cuda_bf16.h>
#include <math.h>
#include <cstdint>

#define BB 4
#define SS 2048
#define DD 1024
#define HH 16
#define HD 64
#define ROWS (BB*SS)   // 8192
#define KTOT 3072      // K' = [hi, lo, hi] x 1024

// ---------------- scratch (no allocs allowed) ----------------
__device__ float g_qn[ROWS*DD];
__device__ float g_v [ROWS*DD];
__device__ float g_proj[ROWS*DD];
__device__ float g_gate[ROWS];
__device__ __nv_bfloat16 g_abuf_q[(size_t)ROWS*KTOT];    // split A for Q proj; reused for O proj
__device__ __nv_bfloat16 g_abuf_k[(size_t)ROWS*KTOT];
__device__ __nv_bfloat16 g_abuf_v[(size_t)ROWS*KTOT];
__device__ __nv_bfloat16 g_wbuf[(size_t)DD*KTOT];        // split-W^T staging
__device__ __nv_bfloat16 g_qsp[(size_t)BB*HH*SS*192];    // per-head Q split [qh|ql|qh]
__device__ __nv_bfloat16 g_ksp[(size_t)BB*HH*SS*192];    // per-head K split [kh|kh|kl]
__device__ __nv_bfloat16 g_vth[(size_t)BB*DD*SS];        // V^T hi
__device__ __nv_bfloat16 g_vtl[(size_t)BB*DD*SS];        // V^T lo

__device__ __forceinline__ uint32_t smem_u32(const void* p) {
    uint32_t a;
    asm("{ .reg .u64 t; cvta.to.shared.u64 t, %1; cvt.u32.u64 %0, t; }" : "=r"(a) : "l"(p));
    return a;
}

#define SWZ128(o) ((o) ^ (((o) >> 3) & 0x70))

__device__ __forceinline__ void ldmx4(uint32_t* r, uint32_t addr) {
    asm volatile("ldmatrix.sync.aligned.m8n8.x4.shared.b16 {%0,%1,%2,%3}, [%4];"
        : "=r"(r[0]), "=r"(r[1]), "=r"(r[2]), "=r"(r[3]) : "r"(addr));
}
__device__ __forceinline__ void mma16816(float* c, const uint32_t* a, const uint32_t* b) {
    asm volatile(
        "mma.sync.aligned.m16n8k16.row.col.f32.bf16.bf16.f32 "
        "{%0,%1,%2,%3}, {%4,%5,%6,%7}, {%8,%9}, {%0,%1,%2,%3};"
        : "+f"(c[0]), "+f"(c[1]), "+f"(c[2]), "+f"(c[3])
        : "r"(a[0]), "r"(a[1]), "r"(a[2]), "r"(a[3]), "r"(b[0]), "r"(b[1]));
}
__device__ __forceinline__ uint32_t packbf(float lo, float hi) {
    uint32_t r;
    asm("cvt.rn.bf16x2.f32 %0, %1, %2;" : "=r"(r) : "f"(hi), "f"(lo));
    return r;
}
#define CPASYNC16(sa, ga) \
    asm volatile("cp.async.cg.shared.global [%0], [%1], 16;" :: "r"(sa), "l"(ga))

// pack (v0,v1) into hi-pair and lo-pair
__device__ __forceinline__ void split_pair(float v0, float v1, uint32_t& hp, uint32_t& lp) {
    __nv_bfloat16 h0 = __float2bfloat16(v0), h1 = __float2bfloat16(v1);
    hp = ((uint32_t)__bfloat16_as_ushort(h1) << 16) | __bfloat16_as_ushort(h0);
    lp = packbf(v0 - __bfloat162float(h0), v1 - __bfloat162float(h1));
}

// ---------------- block reduce ----------------
__device__ __forceinline__ void block_reduce2(float& a, float& b) {
    __shared__ float s1[32], s2[32];
    #pragma unroll
    for (int o = 16; o; o >>= 1) {
        a += __shfl_xor_sync(0xffffffff, a, o);
        b += __shfl_xor_sync(0xffffffff, b, o);
    }
    int w = threadIdx.x >> 5, lane = threadIdx.x & 31;
    int nw = (blockDim.x + 31) >> 5;
    if (lane == 0) { s1[w] = a; s2[w] = b; }
    __syncthreads();
    if (w == 0) {
        a = (lane < nw) ? s1[lane] : 0.f;
        b = (lane < nw) ? s2[lane] : 0.f;
        #pragma unroll
        for (int o = 16; o; o >>= 1) {
            a += __shfl_xor_sync(0xffffffff, a, o);
            b += __shfl_xor_sync(0xffffffff, b, o);
        }
        if (lane == 0) { s1[0] = a; s2[0] = b; }
    }
    __syncthreads();
    a = s1[0]; b = s2[0];
}

// ---------------- layernorm fused with hi/lo split ----------------
__global__ __launch_bounds__(256) void ln_split(const float* __restrict__ x,
                                                const float* __restrict__ gg,
                                                const float* __restrict__ bb,
                                                float* __restrict__ yf,      // may be null
                                                __nv_bfloat16* __restrict__ ys) {
    int row = blockIdx.x;
    const float4* xr = (const float4*)(x + (size_t)row * DD);
    int i = threadIdx.x;
    float4 xv = xr[i];
    float sum = xv.x + xv.y + xv.z + xv.w;
    float sq  = xv.x*xv.x + xv.y*xv.y + xv.z*xv.z + xv.w*xv.w;
    block_reduce2(sum, sq);
    float mu = sum * (1.0f / DD);
    float var = sq * (1.0f / DD) - mu * mu;
    float r = rsqrtf(var + 1e-5f);
    float4 gv = ((const float4*)gg)[i];
    float4 bv = ((const float4*)bb)[i];
    float4 o;
    o.x = (xv.x - mu) * r * gv.x + bv.x;
    o.y = (xv.y - mu) * r * gv.y + bv.y;
    o.z = (xv.z - mu) * r * gv.z + bv.z;
    o.w = (xv.w - mu) * r * gv.w + bv.w;
    if (yf) ((float4*)(yf + (size_t)row * DD))[i] = o;
    uint32_t hp0, lp0, hp1, lp1;
    split_pair(o.x, o.y, hp0, lp0);
    split_pair(o.z, o.w, hp1, lp1);
    size_t base = (size_t)row * KTOT + i * 4;
    *(uint2*)(ys + base)          = make_uint2(hp0, hp1);
    *(uint2*)(ys + base + DD)     = make_uint2(lp0, lp1);
    *(uint2*)(ys + base + 2*DD)   = make_uint2(hp0, hp1);
}

// ---------------- split+transpose W -> bf16 Wt [n][3072] = [Wh | Wh | Wl] ----------------
__global__ __launch_bounds__(256) void split_wt(const float* __restrict__ W,
                                                __nv_bfloat16* __restrict__ Y) {
    __shared__ float t[32][33];
    int k0 = blockIdx.y * 32, n0 = blockIdx.x * 32;
    int tx = threadIdx.x & 31, ty = threadIdx.x >> 5;
    #pragma unroll
    for (int i = 0; i < 32; i += 8)
        t[ty + i][tx] = W[(size_t)(k0 + ty + i) * DD + n0 + tx];
    __syncthreads();
    #pragma unroll
    for (int i = 0; i < 32; i += 8) {
        int n = ty + i;
        float v = t[tx][n];
        __nv_bfloat16 h = __float2bfloat16(v);
        __nv_bfloat16 l = __float2bfloat16(v - __bfloat162float(h));
        size_t base = (size_t)(n0 + n) * KTOT + k0 + tx;
        Y[base]          = h;
        Y[base + DD]     = h;
        Y[base + 2*DD]   = l;
    }
}

// ---------------- V transpose + split ----------------
__global__ __launch_bounds__(256) void vt_split(const float* __restrict__ V,
                                                __nv_bfloat16* __restrict__ Vh,
                                                __nv_bfloat16* __restrict__ Vl) {
    __shared__ float t[32][33];
    int s0 = blockIdx.x * 32, d0 = blockIdx.y * 32, b = blockIdx.z;
    int tx = threadIdx.x & 31, ty = threadIdx.x >> 5;
    #pragma unroll
    for (int i = 0; i < 32; i += 8)
        t[ty + i][tx] = V[((size_t)b * SS + s0 + ty + i) * DD + d0 + tx];
    __syncthreads();
    #pragma unroll
    for (int i = 0; i < 32; i += 8) {
        int d = ty + i;
        float v = t[tx][d];
        __nv_bfloat16 h = __float2bfloat16(v);
        __nv_bfloat16 l = __float2bfloat16(v - __bfloat162float(h));
        size_t o = ((size_t)b * DD + d0 + d) * SS + s0 + tx;
        Vh[o] = h; Vl[o] = l;
    }
}

// ---------------- cp.async double-buffered mma GEMM ----------------
// EMODE 0: f32 out (+bias). EMODE 1: q-split per-head [qh|ql|qh]. EMODE 2: k-split [kh|kh|kl].
#define KC 64
#define NCHUNK (KTOT / KC)   // 48
#define SMEM_GEMM 65536

template<int EMODE>
__global__ __launch_bounds__(256) void gemm_cp(const __nv_bfloat16* __restrict__ A,
                                               const __nv_bfloat16* __restrict__ Bt,
                                               const float* __restrict__ bias,
                                               void* __restrict__ out) {
    extern __shared__ __align__(1024) char smem[];
    uint32_t sb = smem_u32(smem);
    int tid = threadIdx.x;
    int w = tid >> 5, lane = tid & 31;
    int wm = w & 1, wn = w >> 1;
    int row0 = blockIdx.y * 128, col0 = blockIdx.x * 128;

    float acc[4][4][4];
    #pragma unroll
    for (int i = 0; i < 4; i++)
        #pragma unroll
        for (int j = 0; j < 4; j++)
            #pragma unroll
            for (int e = 0; e < 4; e++) acc[i][j][e] = 0.f;

    // prologue: stage chunk 0 into buffer 0
    {
        #pragma unroll
        for (int i = 0; i < 4; i++) {
            int idx = tid + 256 * i;
            int r = idx >> 3, u = idx & 7;
            uint32_t sw = SWZ128((uint32_t)(r * 128 + u * 16));
            CPASYNC16(sb + sw,         (const char*)(A  + (size_t)(row0 + r) * KTOT + u * 8));
            CPASYNC16(sb + 16384 + sw, (const char*)(Bt + (size_t)(col0 + r) * KTOT + u * 8));
        }
        asm volatile("cp.async.commit_group;");
    }

    for (int c = 0; c < NCHUNK; c++) {
        if (c + 1 < NCHUNK) {
            int k0 = (c + 1) * KC;
            uint32_t base = ((c + 1) & 1) * 32768u;
            #pragma unroll
            for (int i = 0; i < 4; i++) {
                int idx = tid + 256 * i;
                int r = idx >> 3, u = idx & 7;
                uint32_t sw = SWZ128((uint32_t)(r * 128 + u * 16));
                CPASYNC16(sb + base + sw,         (const char*)(A  + (size_t)(row0 + r) * KTOT + k0 + u * 8));
                CPASYNC16(sb + base + 16384 + sw, (const char*)(Bt + (size_t)(col0 + r) * KTOT + k0 + u * 8));
            }
            asm volatile("cp.async.commit_group;");
            asm volatile("cp.async.wait_group 1;");
        } else {
            asm volatile("cp.async.wait_group 0;");
        }
        __syncthreads();

        uint32_t cbase = (c & 1) * 32768u;
        #pragma unroll
        for (int k16 = 0; k16 < 4; k16++) {
            uint32_t af[4][4];
            int ar = wm * 64 + (lane & 15);
            int akc = k16 * 16 + (lane >> 4) * 8;
            #pragma unroll
            for (int mt = 0; mt < 4; mt++)
                ldmx4(af[mt], sb + cbase + SWZ128((uint32_t)((ar + mt * 16) * 128 + akc * 2)));
            uint32_t bf[4][2];
            #pragma unroll
            for (int nt2 = 0; nt2 < 2; nt2++) {
                int bn = wn * 32 + nt2 * 16 + (lane & 7) + ((lane & 16) ? 8 : 0);
                int bkc = k16 * 16 + ((lane >> 3) & 1) * 8;
                uint32_t q[4];
                ldmx4(q, sb + cbase + 16384 + SWZ128((uint32_t)(bn * 128 + bkc * 2)));
                bf[nt2 * 2 + 0][0] = q[0]; bf[nt2 * 2 + 0][1] = q[1];
                bf[nt2 * 2 + 1][0] = q[2]; bf[nt2 * 2 + 1][1] = q[3];
            }
            #pragma unroll
            for (int mt = 0; mt < 4; mt++)
                #pragma unroll
                for (int nt = 0; nt < 4; nt++)
                    mma16816(acc[mt][nt], af[mt], bf[nt]);
        }
        __syncthreads();
    }

    // epilogue
    #pragma unroll
    for (int mt = 0; mt < 4; mt++) {
        int crow = row0 + wm * 64 + mt * 16 + (lane >> 2);
        #pragma unroll
        for (int nt = 0; nt < 4; nt++) {
            int ccol = col0 + wn * 32 + nt * 8 + (lane & 3) * 2;
            float2 bv = *(const float2*)&bias[ccol];
            float v0 = acc[mt][nt][0] + bv.x, v1 = acc[mt][nt][1] + bv.y;
            float v2 = acc[mt][nt][2] + bv.x, v3 = acc[mt][nt][3] + bv.y;
            if (EMODE == 0) {
                float* C = (float*)out;
                *(float2*)&C[(size_t)crow * DD + ccol]       = make_float2(v0, v1);
                *(float2*)&C[(size_t)(crow + 8) * DD + ccol] = make_float2(v2, v3);
            } else {
                __nv_bfloat16* Y = (__nv_bfloat16*)out;
                int b = crow >> 11, s = crow & 2047;
                int h = ccol >> 6, cc = ccol & 63;
                size_t base = ((size_t)(b * HH + h) * SS + s) * 192 + cc;
                uint32_t hp, lp;
                split_pair(v0, v1, hp, lp);
                if (EMODE == 1) {
                    *(uint32_t*)(Y + base) = hp;  *(uint32_t*)(Y + base + 64) = lp;  *(uint32_t*)(Y + base + 128) = hp;
                } else {
                    *(uint32_t*)(Y + base) = hp;  *(uint32_t*)(Y + base + 64) = hp;  *(uint32_t*)(Y + base + 128) = lp;
                }
                split_pair(v2, v3, hp, lp);
                size_t base2 = base + 8 * 192;
                if (EMODE == 1) {
                    *(uint32_t*)(Y + base2) = hp; *(uint32_t*)(Y + base2 + 64) = lp; *(uint32_t*)(Y + base2 + 128) = hp;
                } else {
                    *(uint32_t*)(Y + base2) = hp; *(uint32_t*)(Y + base2 + 64) = hp; *(uint32_t*)(Y + base2 + 128) = lp;
                }
            }
        }
    }
}

// ---------------- mma flash attention (validated R11); epilogue now writes [hi|lo|hi] operand ----------------
#define SMEM_ATT 90112

__global__ __launch_bounds__(256) void attn_mma(const __nv_bfloat16* __restrict__ Qs,
                                                const __nv_bfloat16* __restrict__ Ks,
                                                const __nv_bfloat16* __restrict__ Vh,
                                                const __nv_bfloat16* __restrict__ Vl,
                                                __nv_bfloat16* __restrict__ Oa) {
    extern __shared__ __align__(1024) char sm[];
    uint32_t sb = smem_u32(sm);
    const uint32_t SQ = 0, SK = 49152, SVH = 73728, SVL = 81920;
    int tid = threadIdx.x, w = tid >> 5, lane = tid & 31;
    int qt = blockIdx.x, bh = blockIdx.y;
    int b = bh >> 4, h = bh & 15;
    size_t qrow0 = (size_t)bh * SS + qt * 128;
    size_t krow0 = (size_t)bh * SS;
    size_t vrow0 = (size_t)b * DD + h * HD;

    #pragma unroll
    for (int i = 0; i < 12; i++) {
        int idx = tid + 256 * i;
        int row = idx / 24, u = idx % 24;
        uint4 v = *(const uint4*)(Qs + (qrow0 + row) * 192 + u * 8);
        *(uint4*)(sm + SQ + SWZ128((uint32_t)(row * 384 + u * 16))) = v;
    }

    float oacc[8][4];
    #pragma unroll
    for (int nt = 0; nt < 8; nt++)
        #pragma unroll
        for (int e = 0; e < 4; e++) oacc[nt][e] = 0.f;
    float m0 = -1e30f, m1 = -1e30f, l0 = 0.f, l1 = 0.f;

    for (int ch = 0; ch < SS / 64; ch++) {
        __syncthreads();
        #pragma unroll
        for (int i = 0; i < 6; i++) {
            int idx = tid + 256 * i;
            int row = idx / 24, u = idx % 24;
            uint4 v = *(const uint4*)(Ks + (krow0 + ch * 64 + row) * 192 + u * 8);
            *(uint4*)(sm + SK + SWZ128((uint32_t)(row * 384 + u * 16))) = v;
        }
        #pragma unroll
        for (int i = 0; i < 2; i++) {
            int idx = tid + 256 * i;
            int d = idx >> 3, u = idx & 7;
            uint32_t sw = SWZ128((uint32_t)(d * 128 + u * 16));
            *(uint4*)(sm + SVH + sw) = *(const uint4*)(Vh + (vrow0 + d) * SS + ch * 64 + u * 8);
            *(uint4*)(sm + SVL + sw) = *(const uint4*)(Vl + (vrow0 + d) * SS + ch * 64 + u * 8);
        }
        __syncthreads();

        float sf[8][4];
        #pragma unroll
        for (int nt = 0; nt < 8; nt++)
            #pragma unroll
            for (int e = 0; e < 4; e++) sf[nt][e] = 0.f;

        #pragma unroll
        for (int kb = 0; kb < 12; kb++) {
            uint32_t a[4];
            int ar = w * 16 + (lane & 15);
            int akc = kb * 16 + (lane >> 4) * 8;
            ldmx4(a, sb + SQ + SWZ128((uint32_t)(ar * 384 + akc * 2)));
            uint32_t bf[8][2];
            #pragma unroll
            for (int nt2 = 0; nt2 < 4; nt2++) {
                int bn = nt2 * 16 + (lane & 7) + ((lane & 16) ? 8 : 0);
                int bkc = kb * 16 + ((lane >> 3) & 1) * 8;
                uint32_t q[4];
                ldmx4(q, sb + SK + SWZ128((uint32_t)(bn * 384 + bkc * 2)));
                bf[nt2 * 2 + 0][0] = q[0]; bf[nt2 * 2 + 0][1] = q[1];
                bf[nt2 * 2 + 1][0] = q[2]; bf[nt2 * 2 + 1][1] = q[3];
            }
            #pragma unroll
            for (int nt = 0; nt < 8; nt++) mma16816(sf[nt], a, bf[nt]);
        }

        float mr0 = -1e30f, mr1 = -1e30f;
        #pragma unroll
        for (int nt = 0; nt < 8; nt++) {
            #pragma unroll
            for (int e = 0; e < 4; e++) sf[nt][e] *= 0.125f;
            mr0 = fmaxf(mr0, fmaxf(sf[nt][0], sf[nt][1]));
            mr1 = fmaxf(mr1, fmaxf(sf[nt][2], sf[nt][3]));
        }
        mr0 = fmaxf(mr0, __shfl_xor_sync(0xffffffff, mr0, 1));
        mr0 = fmaxf(mr0, __shfl_xor_sync(0xffffffff, mr0, 2));
        mr1 = fmaxf(mr1, __shfl_xor_sync(0xffffffff, mr1, 1));
        mr1 = fmaxf(mr1, __shfl_xor_sync(0xffffffff, mr1, 2));
        float nm0 = fmaxf(m0, mr0), nm1 = fmaxf(m1, mr1);
        float f0 = __expf(m0 - nm0), f1 = __expf(m1 - nm1);
        m0 = nm0; m1 = nm1;
        float s0 = 0.f, s1 = 0.f;
        #pragma unroll
        for (int nt = 0; nt < 8; nt++) {
            sf[nt][0] = __expf(sf[nt][0] - m0);
            sf[nt][1] = __expf(sf[nt][1] - m0);
            sf[nt][2] = __expf(sf[nt][2] - m1);
            sf[nt][3] = __expf(sf[nt][3] - m1);
            s0 += sf[nt][0] + sf[nt][1];
            s1 += sf[nt][2] + sf[nt][3];
        }
        s0 += __shfl_xor_sync(0xffffffff, s0, 1);
        s0 += __shfl_xor_sync(0xffffffff, s0, 2);
        s1 += __shfl_xor_sync(0xffffffff, s1, 1);
        s1 += __shfl_xor_sync(0xffffffff, s1, 2);
        l0 = l0 * f0 + s0;
        l1 = l1 * f1 + s1;
        #pragma unroll
        for (int nt = 0; nt < 8; nt++) {
            oacc[nt][0] *= f0; oacc[nt][1] *= f0;
            oacc[nt][2] *= f1; oacc[nt][3] *= f1;
        }

        uint32_t ah[4][4], al[4][4];
        #pragma unroll
        for (int kb = 0; kb < 4; kb++) {
            #pragma unroll
            for (int half = 0; half < 2; half++) {
                const float* p = sf[2 * kb + half];
                float h0 = __bfloat162float(__float2bfloat16(p[0]));
                float h1 = __bfloat162float(__float2bfloat16(p[1]));
                float h2 = __bfloat162float(__float2bfloat16(p[2]));
                float h3 = __bfloat162float(__float2bfloat16(p[3]));
                ah[kb][half * 2 + 0] = packbf(p[0], p[1]);
                ah[kb][half * 2 + 1] = packbf(p[2], p[3]);
                al[kb][half * 2 + 0] = packbf(p[0] - h0, p[1] - h1);
                al[kb][half * 2 + 1] = packbf(p[2] - h2, p[3] - h3);
            }
        }

        #pragma unroll
        for (int kb = 0; kb < 12; kb++) {
            const uint32_t* a = (kb < 4) ? ah[kb] : (kb < 8) ? al[kb - 4] : ah[kb - 8];
            uint32_t vbase_sm = (kb < 8) ? SVH : SVL;
            int vkb = kb & 3;
            uint32_t bf[8][2];
            #pragma unroll
            for (int nt2 = 0; nt2 < 4; nt2++) {
                int bn = nt2 * 16 + (lane & 7) + ((lane & 16) ? 8 : 0);
                int bkc = vkb * 16 + ((lane >> 3) & 1) * 8;
                uint32_t q[4];
                ldmx4(q, sb + vbase_sm + SWZ128((uint32_t)(bn * 128 + bkc * 2)));
                bf[nt2 * 2 + 0][0] = q[0]; bf[nt2 * 2 + 0][1] = q[1];
                bf[nt2 * 2 + 1][0] = q[2]; bf[nt2 * 2 + 1][1] = q[3];
            }
            #pragma unroll
            for (int nt = 0; nt < 8; nt++) mma16816(oacc[nt], a, bf[nt]);
        }
    }

    // epilogue: write [hi|lo|hi] operand rows for the output projection
    float i0 = 1.f / l0, i1 = 1.f / l1;
    size_t grow = (size_t)b * SS + qt * 128 + w * 16 + (lane >> 2);
    #pragma unroll
    for (int nt = 0; nt < 8; nt++) {
        int col = h * HD + nt * 8 + (lane & 3) * 2;
        float v0 = oacc[nt][0] * i0, v1 = oacc[nt][1] * i0;
        float v2 = oacc[nt][2] * i1, v3 = oacc[nt][3] * i1;
        uint32_t hp, lp;
        size_t base = grow * KTOT + col;
        split_pair(v0, v1, hp, lp);
        *(uint32_t*)(Oa + base)          = hp;
        *(uint32_t*)(Oa + base + DD)     = lp;
        *(uint32_t*)(Oa + base + 2*DD)   = hp;
        split_pair(v2, v3, hp, lp);
        size_t base2 = base + 8 * KTOT;
        *(uint32_t*)(Oa + base2)         = hp;
        *(uint32_t*)(Oa + base2 + DD)    = lp;
        *(uint32_t*)(Oa + base2 + 2*DD)  = hp;
    }
}

// ---------------- gate GEMV ----------------
__global__ __launch_bounds__(128) void gate_kernel(const float* __restrict__ qn,
                                                   const float* __restrict__ Wg,
                                                   float* __restrict__ gate) {
    int row = blockIdx.x;
    const float4* xr = (const float4*)(qn + (size_t)row * DD);
    const float4* wr = (const float4*)Wg;
    float s = 0.f;
    #pragma unroll
    for (int i = threadIdx.x; i < DD / 4; i += 128) {
        float4 xv = xr[i];
        float4 wv = wr[i];
        s += xv.x * wv.x + xv.y * wv.y + xv.z * wv.z + xv.w * wv.w;
    }
    float dummy = 0.f;
    block_reduce2(s, dummy);
    if (threadIdx.x == 0) gate[row] = 1.0f / (1.0f + __expf(-s));
}

// ---------------- final: out = LN(gate * proj) ----------------
__global__ __launch_bounds__(256) void final_kernel(const float* __restrict__ proj,
                                                    const float* __restrict__ gate,
                                                    const float* __restrict__ gg,
                                                    const float* __restrict__ bb,
                                                    float* __restrict__ out) {
    int row = blockIdx.x;
    float gt = gate[row];
    const float4* xr = (const float4*)(proj + (size_t)row * DD);
    int i = threadIdx.x;
    float4 xv = xr[i];
    xv.x *= gt; xv.y *= gt; xv.z *= gt; xv.w *= gt;
    float sum = xv.x + xv.y + xv.z + xv.w;
    float sq  = xv.x*xv.x + xv.y*xv.y + xv.z*xv.z + xv.w*xv.w;
    block_reduce2(sum, sq);
    float mu = sum * (1.0f / DD);
    float var = sq * (1.0f / DD) - mu * mu;
    float r = rsqrtf(var + 1e-5f);
    float4 gv = ((const float4*)gg)[i];
    float4 bv = ((const float4*)bb)[i];
    float4 o;
    o.x = (xv.x - mu) * r * gv.x + bv.x;
    o.y = (xv.y - mu) * r * gv.y + bv.y;
    o.z = (xv.z - mu) * r * gv.z + bv.z;
    o.w = (xv.w - mu) * r * gv.w + bv.w;
    ((float4*)(out + (size_t)row * DD))[i] = o;
}

// ---------------- launch ----------------
extern "C" void kernel_launch(void* const* d_in, const int* in_sizes, int n_in,
                              void* d_out, int out_size) {
    const float* query = (const float*)d_in[0];
    const float* key   = (const float*)d_in[1];
    const float* value = (const float*)d_in[2];
    const float* Wq = (const float*)d_in[3];
    const float* bq = (const float*)d_in[4];
    const float* Wk = (const float*)d_in[5];
    const float* bk = (const float*)d_in[6];
    const float* Wv = (const float*)d_in[7];
    const float* bv = (const float*)d_in[8];
    const float* Wo = (const float*)d_in[9];
    const float* bo = (const float*)d_in[10];
    const float* Wg = (const float*)d_in[11];
    const float* ln_q_g  = (const float*)d_in[12];
    const float* ln_q_b  = (const float*)d_in[13];
    const float* ln_kv_g = (const float*)d_in[14];
    const float* ln_kv_b = (const float*)d_in[15];
    const float* ln_o_g  = (const float*)d_in[16];
    const float* ln_o_b  = (const float*)d_in[17];
    float* out = (float*)d_out;

    float *qn, *v, *proj, *gate;
    __nv_bfloat16 *aq, *ak, *av, *wbuf, *qsp, *ksp, *vth, *vtl;
    cudaGetSymbolAddress((void**)&qn,   g_qn);
    cudaGetSymbolAddress((void**)&v,    g_v);
    cudaGetSymbolAddress((void**)&proj, g_proj);
    cudaGetSymbolAddress((void**)&gate, g_gate);
    cudaGetSymbolAddress((void**)&aq,   g_abuf_q);
    cudaGetSymbolAddress((void**)&ak,   g_abuf_k);
    cudaGetSymbolAddress((void**)&av,   g_abuf_v);
    cudaGetSymbolAddress((void**)&wbuf, g_wbuf);
    cudaGetSymbolAddress((void**)&qsp,  g_qsp);
    cudaGetSymbolAddress((void**)&ksp,  g_ksp);
    cudaGetSymbolAddress((void**)&vth,  g_vth);
    cudaGetSymbolAddress((void**)&vtl,  g_vtl);

    cudaFuncSetAttribute(attn_mma,   cudaFuncAttributeMaxDynamicSharedMemorySize, SMEM_ATT);
    cudaFuncSetAttribute(gemm_cp<0>, cudaFuncAttributeMaxDynamicSharedMemorySize, SMEM_GEMM);
    cudaFuncSetAttribute(gemm_cp<1>, cudaFuncAttributeMaxDynamicSharedMemorySize, SMEM_GEMM);
    cudaFuncSetAttribute(gemm_cp<2>, cudaFuncAttributeMaxDynamicSharedMemorySize, SMEM_GEMM);

    // 1. pre-norms fused with operand split
    ln_split<<<ROWS, 256>>>(query, ln_q_g,  ln_q_b,  qn,      aq);
    ln_split<<<ROWS, 256>>>(key,   ln_kv_g, ln_kv_b, nullptr, ak);
    ln_split<<<ROWS, 256>>>(value, ln_kv_g, ln_kv_b, nullptr, av);

    // 2. gate
    gate_kernel<<<ROWS, 128>>>(qn, Wg, gate);

    // 3. projections; Q/K write per-head attention operands directly
    dim3 ggrid(DD / 128, ROWS / 128);
    dim3 wgrid(DD / 32, DD / 32);

    split_wt<<<wgrid, 256>>>(Wq, wbuf);
    gemm_cp<1><<<ggrid, 256, SMEM_GEMM>>>(aq, wbuf, bq, qsp);

    split_wt<<<wgrid, 256>>>(Wk, wbuf);
    gemm_cp<2><<<ggrid, 256, SMEM_GEMM>>>(ak, wbuf, bk, ksp);

    split_wt<<<wgrid, 256>>>(Wv, wbuf);
    gemm_cp<0><<<ggrid, 256, SMEM_GEMM>>>(av, wbuf, bv, v);

    // 4. V transpose + attention (epilogue writes O-proj operand into aq)
    dim3 vgrid(SS / 32, DD / 32, BB);
    vt_split<<<vgrid, 256>>>(v, vth, vtl);
    dim3 agrid(SS / 128, BB * HH);
    attn_mma<<<agrid, 256, SMEM_ATT>>>(qsp, ksp, vth, vtl, aq);

    // 5. output projection
    split_wt<<<wgrid, 256>>>(Wo, wbuf);
    gemm_cp<0><<<ggrid, 256, SMEM_GEMM>>>(aq, wbuf, bo, proj);

    // 6. gate * proj -> final LN
    final_kernel<<<ROWS, 256>>>(proj, gate, ln_o_g, ln_o_b, out);
}